// round 16
// baseline (speedup 1.0000x reference)
#include <cuda_runtime.h>

// feature_maps: [S=2, B=8, C=32, H=128, W=128] fp32
// boxes:        [S=2, B=8, M=16, 4] fp32 (x1, y1, x3, y3), strictly inside the
//               map, width/height in [16, 40] -> all bilinear taps in-bounds.
// output:       [S, B*M=128, C=32, 128, 128] fp32
//
// Converged design (R6 config; write-roofline bound at ~5.66 TB/s).
// This round's single change: st.global.cs -> st.global.wt (write-through),
// probing whether bypassing L2 dirty-writeback improves DRAM write burst
// locality. Everything else identical to the best-measured kernel.
#define S_DIM 2
#define B_DIM 8
#define M_DIM 16
#define C_DIM 32
#define H_DIM 128
#define W_DIM 128
#define OUT_W 128
#define OUT_H 128
#define ROWS_PER_BLK 64          // output rows per block (half a crop)
#define MAX_SRC_ROWS 24          // 63*dy <= 19.7 -> <= 22 source rows needed

__device__ __forceinline__ void stwt4(float* p, float4 v) {
    asm volatile("st.global.wt.v4.f32 [%0], {%1, %2, %3, %4};"
                 :: "l"(p), "f"(v.x), "f"(v.y), "f"(v.z), "f"(v.w) : "memory");
}

__global__ __launch_bounds__(128, 12)
void rroi_crop_kernel(const float* __restrict__ fm,
                      const float* __restrict__ boxes,
                      float* __restrict__ out)
{
    __shared__ float fx_s[MAX_SRC_ROWS * OUT_W];   // x-interpolated source rows

    const int c    = blockIdx.x;       // channel 0..31
    const int p    = blockIdx.y;       // crop 0..255 = s*B*M + b*M + m
    const int half = blockIdx.z;       // 0: rows 0..63, 1: rows 64..127
    const int tid  = threadIdx.x;

    const int s = p >> 7;
    const int b = (p >> 4) & 7;

    const float4 box = __ldg(((const float4*)boxes) + p);
    const float x1 = box.x, y1 = box.y, x3 = box.z, y3 = box.w;

    const float* __restrict__ f = fm + ((((s * B_DIM + b) * C_DIM) + c) << 14);

    const float dy      = (y3 - y1) * (1.0f / (float)OUT_H);
    const int   v_base  = half << 6;                         // 0 or 64
    const int   y_lo    = (int)floorf(fmaf((float)v_base, dy, y1));
    const float sy_last = fmaf((float)(v_base + ROWS_PER_BLK - 1), dy, y1);
    const int   ny      = ((int)floorf(sy_last)) - y_lo + 2; // <= 22

    // ---- Pass A: x-interpolate the needed source rows into smem ----
    {
        const float dx  = (x3 - x1) * (1.0f / (float)OUT_W);
        const float sx  = fmaf((float)tid, dx, x1);
        const float x0f = floorf(sx);
        const float wx  = sx - x0f;
        const float w0  = 1.0f - wx;
        const int   x0  = (int)x0f;                          // in [0,126]
        const float* __restrict__ col = f + (y_lo << 7) + x0;

        #pragma unroll 4
        for (int i = 0; i < ny; ++i) {
            const float a  = __ldg(col + (i << 7));
            const float bb = __ldg(col + (i << 7) + 1);
            fx_s[(i << 7) + tid] = fmaf(bb, wx, a * w0);
        }
    }
    __syncthreads();

    // ---- Pass B: warp-strip y-lerp, register-cached source rows ----
    // Warp w handles 16 output rows (one linear 8KB store stream); lane
    // handles 4 consecutive columns. Source row pair is warp-uniform and
    // advances by at most 1 per step (dy <= 0.32).
    const int lane = tid & 31;
    const int w    = tid >> 5;
    const int q    = lane << 2;
    float* __restrict__ o = out + (((p * C_DIM) + c) << 14) + q;

    const int   v0  = v_base + (w << 4);
    const float sy0 = fmaf((float)v0, dy, y1);
    int cur = (((int)floorf(sy0)) - y_lo) << 7;              // offset in fx_s

    float4 ra = *(const float4*)(fx_s + cur + q);
    float4 rb = *(const float4*)(fx_s + cur + OUT_W + q);

    #pragma unroll 8
    for (int i = 0; i < 16; ++i) {
        const int   v   = v0 + i;
        const float sy  = fmaf((float)v, dy, y1);
        const float y0f = floorf(sy);
        const float wy  = sy - y0f;
        const int   off = (((int)y0f) - y_lo) << 7;

        if (off != cur) {                                    // warp-uniform, +1 row
            ra  = rb;
            rb  = *(const float4*)(fx_s + off + OUT_W + q);
            cur = off;
        }

        float4 res;
        res.x = fmaf(wy, rb.x - ra.x, ra.x);
        res.y = fmaf(wy, rb.y - ra.y, ra.y);
        res.z = fmaf(wy, rb.z - ra.z, ra.z);
        res.w = fmaf(wy, rb.w - ra.w, ra.w);
        stwt4(o + (v << 7), res);                            // write-through store
    }
}

extern "C" void kernel_launch(void* const* d_in, const int* in_sizes, int n_in,
                              void* d_out, int out_size)
{
    const float* fm    = (const float*)d_in[0];
    const float* boxes = (const float*)d_in[1];
    float*       out   = (float*)d_out;

    dim3 grid(C_DIM, S_DIM * B_DIM * M_DIM, 2);   // (32, 256, 2)
    rroi_crop_kernel<<<grid, 128>>>(fm, boxes, out);
}

// round 17
// speedup vs baseline: 1.0896x; 1.0896x over previous
#include <cuda_runtime.h>

// feature_maps: [S=2, B=8, C=32, H=128, W=128] fp32
// boxes:        [S=2, B=8, M=16, 4] fp32 (x1, y1, x3, y3), strictly inside the
//               map, width/height in [16, 40] -> all bilinear taps in-bounds.
// output:       [S, B*M=128, C=32, 128, 128] fp32
//
// FINAL kernel (converged at the HBM streaming-write roofline):
//   - one block = half a (crop, channel) output tile -> 16384 blocks, 128 thr
//   - Pass A: separable x-interpolation of <=22 source rows into smem
//     (each x-interpolated row serves ~3 output rows; reads are L2-resident)
//   - Pass B: warp-strip y-lerp; warp owns 16 consecutive output rows (one
//     linear 8KB store stream), lane owns 4 columns; source row pair cached
//     in registers with warp-uniform advance (<=1 row/step since dy<=0.32)
//   - st.global.cs.v4 streaming stores (evict-first; .wt measured worse)
//   - 512MB output / ~5.66TB/s achieved write bandwidth ~= 85.5us
//
// Probes that established the ceiling: instruction count (24->7 instr/16B),
// occupancy 46-91%, 128/256-thread blocks, persistent grid, launch-order
// address locality, halved read traffic, write-through stores. All flat or
// worse; DRAM write drain is the binding resource.
#define S_DIM 2
#define B_DIM 8
#define M_DIM 16
#define C_DIM 32
#define H_DIM 128
#define W_DIM 128
#define OUT_W 128
#define OUT_H 128
#define ROWS_PER_BLK 64          // output rows per block (half a crop)
#define MAX_SRC_ROWS 24          // 63*dy <= 19.7 -> <= 22 source rows needed

__device__ __forceinline__ void stcs4(float* p, float4 v) {
    asm volatile("st.global.cs.v4.f32 [%0], {%1, %2, %3, %4};"
                 :: "l"(p), "f"(v.x), "f"(v.y), "f"(v.z), "f"(v.w) : "memory");
}

__global__ __launch_bounds__(128, 12)
void rroi_crop_kernel(const float* __restrict__ fm,
                      const float* __restrict__ boxes,
                      float* __restrict__ out)
{
    __shared__ float fx_s[MAX_SRC_ROWS * OUT_W];   // x-interpolated source rows

    const int c    = blockIdx.x;       // channel 0..31
    const int p    = blockIdx.y;       // crop 0..255 = s*B*M + b*M + m
    const int half = blockIdx.z;       // 0: rows 0..63, 1: rows 64..127
    const int tid  = threadIdx.x;

    const int s = p >> 7;
    const int b = (p >> 4) & 7;

    const float4 box = __ldg(((const float4*)boxes) + p);
    const float x1 = box.x, y1 = box.y, x3 = box.z, y3 = box.w;

    const float* __restrict__ f = fm + ((((s * B_DIM + b) * C_DIM) + c) << 14);

    const float dy      = (y3 - y1) * (1.0f / (float)OUT_H);
    const int   v_base  = half << 6;                         // 0 or 64
    const int   y_lo    = (int)floorf(fmaf((float)v_base, dy, y1));
    const float sy_last = fmaf((float)(v_base + ROWS_PER_BLK - 1), dy, y1);
    const int   ny      = ((int)floorf(sy_last)) - y_lo + 2; // <= 22

    // ---- Pass A: x-interpolate the needed source rows into smem ----
    {
        const float dx  = (x3 - x1) * (1.0f / (float)OUT_W);
        const float sx  = fmaf((float)tid, dx, x1);
        const float x0f = floorf(sx);
        const float wx  = sx - x0f;
        const float w0  = 1.0f - wx;
        const int   x0  = (int)x0f;                          // in [0,126]
        const float* __restrict__ col = f + (y_lo << 7) + x0;

        #pragma unroll 4
        for (int i = 0; i < ny; ++i) {
            const float a  = __ldg(col + (i << 7));
            const float bb = __ldg(col + (i << 7) + 1);
            fx_s[(i << 7) + tid] = fmaf(bb, wx, a * w0);
        }
    }
    __syncthreads();

    // ---- Pass B: warp-strip y-lerp, register-cached source rows ----
    const int lane = tid & 31;
    const int w    = tid >> 5;
    const int q    = lane << 2;
    float* __restrict__ o = out + (((p * C_DIM) + c) << 14) + q;

    const int   v0  = v_base + (w << 4);
    const float sy0 = fmaf((float)v0, dy, y1);
    int cur = (((int)floorf(sy0)) - y_lo) << 7;              // offset in fx_s

    float4 ra = *(const float4*)(fx_s + cur + q);
    float4 rb = *(const float4*)(fx_s + cur + OUT_W + q);

    #pragma unroll 8
    for (int i = 0; i < 16; ++i) {
        const int   v   = v0 + i;
        const float sy  = fmaf((float)v, dy, y1);
        const float y0f = floorf(sy);
        const float wy  = sy - y0f;
        const int   off = (((int)y0f) - y_lo) << 7;

        if (off != cur) {                                    // warp-uniform, +1 row
            ra  = rb;
            rb  = *(const float4*)(fx_s + off + OUT_W + q);
            cur = off;
        }

        float4 res;
        res.x = fmaf(wy, rb.x - ra.x, ra.x);
        res.y = fmaf(wy, rb.y - ra.y, ra.y);
        res.z = fmaf(wy, rb.z - ra.z, ra.z);
        res.w = fmaf(wy, rb.w - ra.w, ra.w);
        stcs4(o + (v << 7), res);                            // streaming store
    }
}

extern "C" void kernel_launch(void* const* d_in, const int* in_sizes, int n_in,
                              void* d_out, int out_size)
{
    const float* fm    = (const float*)d_in[0];
    const float* boxes = (const float*)d_in[1];
    float*       out   = (float*)d_out;

    dim3 grid(C_DIM, S_DIM * B_DIM * M_DIM, 2);   // (32, 256, 2)
    rroi_crop_kernel<<<grid, 128>>>(fm, boxes, out);
}